// round 1
// baseline (speedup 1.0000x reference)
#include <cuda_runtime.h>

#define BATCH 16384
#define BAG   30
#define H1    256
#define H2    32

// Inputs (metadata order):
// 0: white_indices int32 [B*BAG]
// 1: white_offsets (ignored)
// 2: black_indices int32 [B*BAG]
// 3: black_offsets (ignored)
// 4: ft_white f32 [41025, 256]
// 5: ft_black f32 [41025, 256]
// 6: fc1_w f32 [32, 512]
// 7: fc1_b f32 [32]
// 8: fc2_w f32 [32, 32]
// 9: fc2_b f32 [32]
// 10: fc3_w f32 [1, 32]
// 11: fc3_b f32 [1]
// out: f32 [B]

__global__ __launch_bounds__(256, 8)
void nnue_kernel(const int* __restrict__ wi,
                 const int* __restrict__ bi,
                 const float* __restrict__ ftw,
                 const float* __restrict__ ftb,
                 const float* __restrict__ fc1w,
                 const float* __restrict__ fc1b,
                 const float* __restrict__ fc2w,
                 const float* __restrict__ fc2b,
                 const float* __restrict__ fc3w,
                 const float* __restrict__ fc3b,
                 float* __restrict__ out)
{
    __shared__ int   sidx[2][BAG];
    __shared__ float x[2 * H1];     // concat(white, black) after relu
    __shared__ float h1[H2];

    const int p    = blockIdx.x;
    const int tid  = threadIdx.x;
    const int lane = tid & 31;
    const int warp = tid >> 5;

    // Load the 2x30 indices for this position into smem.
    if (tid < BAG) {
        sidx[0][tid] = wi[p * BAG + tid];
    } else if (tid >= 32 && tid < 32 + BAG) {
        sidx[1][tid - 32] = bi[p * BAG + (tid - 32)];
    }
    __syncthreads();

    // EmbeddingBag sum: thread tid owns column tid of each table.
    // 60 independent LDGs per thread -> high MLP, coalesced 128B/warp.
    float accw = 0.0f, accb = 0.0f;
#pragma unroll 6
    for (int j = 0; j < BAG; j++) {
        const int iw = sidx[0][j];
        const int ib = sidx[1][j];
        accw += __ldg(&ftw[(size_t)iw * H1 + tid]);
        accb += __ldg(&ftb[(size_t)ib * H1 + tid]);
    }
    x[tid]      = fmaxf(accw, 0.0f);
    x[tid + H1] = fmaxf(accb, 0.0f);
    __syncthreads();

    // FC1: 512 -> 32, relu. 8 warps, 4 outputs each; 16 MACs/lane/output
    // then butterfly reduce.
#pragma unroll
    for (int q = 0; q < 4; q++) {
        const int o = warp * 4 + q;
        const float* wrow = fc1w + (size_t)o * 512;
        float part = 0.0f;
#pragma unroll
        for (int i = 0; i < 16; i++) {
            part += x[lane + 32 * i] * __ldg(&wrow[lane + 32 * i]);
        }
#pragma unroll
        for (int off = 16; off > 0; off >>= 1)
            part += __shfl_xor_sync(0xffffffffu, part, off);
        if (lane == 0)
            h1[o] = fmaxf(part + __ldg(&fc1b[o]), 0.0f);
    }
    __syncthreads();

    // FC2 (32->32, relu) + FC3 (32->1) on warp 0.
    if (warp == 0) {
        float s = __ldg(&fc2b[lane]);
        const float* w2 = fc2w + (size_t)lane * 32;
#pragma unroll
        for (int j = 0; j < 32; j++)
            s += h1[j] * __ldg(&w2[j]);
        float v = fmaxf(s, 0.0f) * __ldg(&fc3w[lane]);
#pragma unroll
        for (int off = 16; off > 0; off >>= 1)
            v += __shfl_xor_sync(0xffffffffu, v, off);
        if (lane == 0)
            out[p] = v + __ldg(&fc3b[0]);
    }
}

extern "C" void kernel_launch(void* const* d_in, const int* in_sizes, int n_in,
                              void* d_out, int out_size)
{
    const int*   wi   = (const int*)d_in[0];
    const int*   bi   = (const int*)d_in[2];
    const float* ftw  = (const float*)d_in[4];
    const float* ftb  = (const float*)d_in[5];
    const float* fc1w = (const float*)d_in[6];
    const float* fc1b = (const float*)d_in[7];
    const float* fc2w = (const float*)d_in[8];
    const float* fc2b = (const float*)d_in[9];
    const float* fc3w = (const float*)d_in[10];
    const float* fc3b = (const float*)d_in[11];
    float* out = (float*)d_out;

    nnue_kernel<<<BATCH, 256>>>(wi, bi, ftw, ftb, fc1w, fc1b,
                                fc2w, fc2b, fc3w, fc3b, out);
}

// round 2
// speedup vs baseline: 1.0011x; 1.0011x over previous
#include <cuda_runtime.h>

#define BATCH 16384
#define BAG   30
#define H1    256
#define H2    32

// Inputs (metadata order):
// 0: white_indices int32 [B*BAG]
// 1: white_offsets (ignored)
// 2: black_indices int32 [B*BAG]
// 3: black_offsets (ignored)
// 4: ft_white f32 [41025, 256]
// 5: ft_black f32 [41025, 256]
// 6: fc1_w f32 [32, 512]
// 7: fc1_b f32 [32]
// 8: fc2_w f32 [32, 32]
// 9: fc2_b f32 [32]
// 10: fc3_w f32 [1, 32]
// 11: fc3_b f32 [1]
// out: f32 [B]

__global__ __launch_bounds__(256, 8)
void nnue_kernel(const int* __restrict__ wi,
                 const int* __restrict__ bi,
                 const float* __restrict__ ftw,
                 const float* __restrict__ ftb,
                 const float* __restrict__ fc1w,
                 const float* __restrict__ fc1b,
                 const float* __restrict__ fc2w,
                 const float* __restrict__ fc2b,
                 const float* __restrict__ fc3w,
                 const float* __restrict__ fc3b,
                 float* __restrict__ out)
{
    __shared__ int   sidx[2][BAG];
    __shared__ float x[2 * H1];     // concat(white, black) after relu
    __shared__ float h1[H2];

    const int p    = blockIdx.x;
    const int tid  = threadIdx.x;
    const int lane = tid & 31;
    const int warp = tid >> 5;

    // Load the 2x30 indices for this position into smem.
    if (tid < BAG) {
        sidx[0][tid] = wi[p * BAG + tid];
    } else if (tid >= 32 && tid < 32 + BAG) {
        sidx[1][tid - 32] = bi[p * BAG + (tid - 32)];
    }
    __syncthreads();

    // EmbeddingBag sum: thread tid owns column tid of each table.
    // 60 independent LDGs per thread -> high MLP, coalesced 128B/warp.
    float accw = 0.0f, accb = 0.0f;
#pragma unroll 6
    for (int j = 0; j < BAG; j++) {
        const int iw = sidx[0][j];
        const int ib = sidx[1][j];
        accw += __ldg(&ftw[(size_t)iw * H1 + tid]);
        accb += __ldg(&ftb[(size_t)ib * H1 + tid]);
    }
    x[tid]      = fmaxf(accw, 0.0f);
    x[tid + H1] = fmaxf(accb, 0.0f);
    __syncthreads();

    // FC1: 512 -> 32, relu. 8 warps, 4 outputs each; 16 MACs/lane/output
    // then butterfly reduce.
#pragma unroll
    for (int q = 0; q < 4; q++) {
        const int o = warp * 4 + q;
        const float* wrow = fc1w + (size_t)o * 512;
        float part = 0.0f;
#pragma unroll
        for (int i = 0; i < 16; i++) {
            part += x[lane + 32 * i] * __ldg(&wrow[lane + 32 * i]);
        }
#pragma unroll
        for (int off = 16; off > 0; off >>= 1)
            part += __shfl_xor_sync(0xffffffffu, part, off);
        if (lane == 0)
            h1[o] = fmaxf(part + __ldg(&fc1b[o]), 0.0f);
    }
    __syncthreads();

    // FC2 (32->32, relu) + FC3 (32->1) on warp 0.
    if (warp == 0) {
        float s = __ldg(&fc2b[lane]);
        const float* w2 = fc2w + (size_t)lane * 32;
#pragma unroll
        for (int j = 0; j < 32; j++)
            s += h1[j] * __ldg(&w2[j]);
        float v = fmaxf(s, 0.0f) * __ldg(&fc3w[lane]);
#pragma unroll
        for (int off = 16; off > 0; off >>= 1)
            v += __shfl_xor_sync(0xffffffffu, v, off);
        if (lane == 0)
            out[p] = v + __ldg(&fc3b[0]);
    }
}

extern "C" void kernel_launch(void* const* d_in, const int* in_sizes, int n_in,
                              void* d_out, int out_size)
{
    const int*   wi   = (const int*)d_in[0];
    const int*   bi   = (const int*)d_in[2];
    const float* ftw  = (const float*)d_in[4];
    const float* ftb  = (const float*)d_in[5];
    const float* fc1w = (const float*)d_in[6];
    const float* fc1b = (const float*)d_in[7];
    const float* fc2w = (const float*)d_in[8];
    const float* fc2b = (const float*)d_in[9];
    const float* fc3w = (const float*)d_in[10];
    const float* fc3b = (const float*)d_in[11];
    float* out = (float*)d_out;

    nnue_kernel<<<BATCH, 256>>>(wi, bi, ftw, ftb, fc1w, fc1b,
                                fc2w, fc2b, fc3w, fc3b, out);
}